// round 6
// baseline (speedup 1.0000x reference)
#include <cuda_runtime.h>
#include <cuda_fp16.h>
#include <cstdint>

#define B 8
#define N 4096
#define D 1024
#define H 1024
#define NQ 64
#define H2 2048
#define TOPK 1024

// ---------------- scratch ----------------------------------------------------
__device__ float g_QWf[NQ * D];                 // fp32 QW [q][d]
__device__ __align__(16) uint2 g_Bfrag[32768];  // fp16 MMA-fragment-ordered B
__device__ float g_qbi[NQ];                     // qb/32 + b2
__device__ float g_dbias[B * N];
__device__ float g_S[B * NQ * N];
__device__ float g_pmax[B * 32 * NQ];
__device__ float g_psum[B * 32 * NQ];
__device__ float g_c[B * NQ];
__device__ float g_imp[B * N];
__device__ int   g_flag[B * N];
__device__ int   g_idx[B * TOPK];
__device__ float g_C1, g_C2;
__device__ int   g_bz;

// ---------------- helpers ----------------------------------------------------
__device__ __forceinline__ uint32_t pack_h2(float a, float b) {
    __half2 h = __floats2half2_rn(a, b);
    return *reinterpret_cast<uint32_t*>(&h);
}
__device__ __forceinline__ float2 unpack_h2(uint32_t u) {
    __half2 h = *reinterpret_cast<__half2*>(&u);
    return __half22float2(h);
}
__device__ __forceinline__ void mma_f16(float* d, const uint32_t* a, uint32_t b0, uint32_t b1) {
    asm volatile("mma.sync.aligned.m16n8k16.row.col.f32.f16.f16.f32 "
        "{%0,%1,%2,%3}, {%4,%5,%6,%7}, {%8,%9}, {%0,%1,%2,%3};"
        : "+f"(d[0]), "+f"(d[1]), "+f"(d[2]), "+f"(d[3])
        : "r"(a[0]), "r"(a[1]), "r"(a[2]), "r"(a[3]), "r"(b0), "r"(b1));
}
__device__ __forceinline__ void cp_async16(void* dst_smem, const void* src) {
    uint32_t d;
    asm("{ .reg .u64 t; cvta.to.shared.u64 t, %1; cvt.u32.u64 %0, t; }" : "=r"(d) : "l"(dst_smem));
    asm volatile("cp.async.ca.shared.global [%0], [%1], 16;" :: "r"(d), "l"(src) : "memory");
}
#define CP_COMMIT() asm volatile("cp.async.commit_group;" ::: "memory")
#define CP_WAIT(n)  asm volatile("cp.async.wait_group %0;" :: "n"(n) : "memory")

// ---------------- kernel 0: init (qbi + density consts) ----------------------
__global__ void k_init(const float* __restrict__ qe, const float* __restrict__ kb,
                       const float* __restrict__ b2, const float* __restrict__ w1,
                       const float* __restrict__ b1, const float* __restrict__ w2) {
    int tid = threadIdx.x;
    if (blockIdx.x == 0) {
        int w = tid >> 5, l = tid & 31;
        float b2v = b2[0];
#pragma unroll
        for (int qi = 0; qi < 8; qi++) {
            int q = w * 8 + qi;
            float acc = 0.f;
#pragma unroll
            for (int k = 0; k < 32; k++)
                acc = fmaf(qe[(size_t)q * H + k * 32 + l], kb[k * 32 + l], acc);
#pragma unroll
            for (int o = 16; o; o >>= 1) acc += __shfl_xor_sync(~0u, acc, o);
            if (l == 0) g_qbi[q] = acc * 0.03125f + b2v;
        }
    } else {
        __shared__ float r1[256], r2[256];
        __shared__ int rz[256];
        float c1 = 0.f, c2 = 0.f; int bz = 1;
        for (int j = tid; j < H2; j += 256) {
            float a = w1[j], c = w2[j];
            if (a > 0.f) c1 += a * c; else c2 += a * c;
            if (b1[j] != 0.f) bz = 0;
        }
        r1[tid] = c1; r2[tid] = c2; rz[tid] = bz;
        __syncthreads();
        for (int o = 128; o; o >>= 1) {
            if (tid < o) { r1[tid] += r1[tid + o]; r2[tid] += r2[tid + o]; rz[tid] &= rz[tid + o]; }
            __syncthreads();
        }
        if (tid == 0) { g_C1 = r1[0]; g_C2 = r2[0]; g_bz = rz[0]; }
    }
}

// ---------------- kernel 1: QW GEMM (fp32) -----------------------------------
__global__ void __launch_bounds__(256) k_qw(const float* __restrict__ qe,
                                            const float* __restrict__ kw) {
    __shared__ float skw[8][68];
    __shared__ float sqt[64][65];
    int d0 = blockIdx.x * 8;
    int tid = threadIdx.x;
    int q = tid & 63, dp = tid >> 6;
    float acc0 = 0.f, acc1 = 0.f;
    for (int k0 = 0; k0 < H; k0 += 64) {
#pragma unroll
        for (int r = 0; r < 2; r++) {
            int idx = tid + 256 * r;
            skw[idx >> 6][idx & 63] = kw[(size_t)(d0 + (idx >> 6)) * H + k0 + (idx & 63)];
        }
#pragma unroll
        for (int r = 0; r < 4; r++) {
            int idx = tid + 256 * r;
            int row = idx >> 4, c4 = (idx & 15) * 4;
            float4 v = *(const float4*)(qe + (size_t)row * H + k0 + c4);
            sqt[c4 + 0][row] = v.x; sqt[c4 + 1][row] = v.y;
            sqt[c4 + 2][row] = v.z; sqt[c4 + 3][row] = v.w;
        }
        __syncthreads();
#pragma unroll 8
        for (int k = 0; k < 64; k++) {
            float qv = sqt[k][q];
            acc0 = fmaf(skw[dp][k], qv, acc0);
            acc1 = fmaf(skw[dp + 4][k], qv, acc1);
        }
        __syncthreads();
    }
    g_QWf[(size_t)q * D + d0 + dp] = acc0;
    g_QWf[(size_t)q * D + d0 + dp + 4] = acc1;
}

// ---------------- kernel 2: pack B into fp16 fragment order ------------------
__global__ void k_bfrag() {
    int t = blockIdx.x * 256 + threadIdx.x;   // < 32768
    int lane = t & 31, pl = (t >> 5) & 1, j = (t >> 6) & 7, s = (t >> 9) & 1, c = t >> 10;
    int q = j * 8 + (lane >> 2);
    int k0 = c * 32 + s * 16 + (lane & 3) * 2;
    const float* w = g_QWf + (size_t)q * D + k0;
    float f0 = w[0], f1 = w[1], f2 = w[8], f3 = w[9];
    uint32_t ha = pack_h2(f0, f1), hb = pack_h2(f2, f3);
    if (pl == 0) {
        g_Bfrag[t] = make_uint2(ha, hb);
    } else {
        float2 ca = unpack_h2(ha), cb = unpack_h2(hb);
        g_Bfrag[t] = make_uint2(pack_h2(f0 - ca.x, f1 - ca.y),
                                pack_h2(f2 - cb.x, f3 - cb.y));
    }
}

// ---------------- kernel 3: density bias -------------------------------------
__global__ void k_db(const float* __restrict__ dens, const float* __restrict__ w1,
                     const float* __restrict__ b1, const float* __restrict__ w2) {
    int t = blockIdx.x * 256 + threadIdx.x;
    float d = dens[t];
    if (g_bz) {
        g_dbias[t] = d * (d >= 0.f ? g_C1 : g_C2);
    } else {
        float acc = 0.f;
        for (int j = 0; j < H2; j++)
            acc = fmaf(fmaxf(fmaf(d, w1[j], b1[j]), 0.f), w2[j], acc);
        g_dbias[t] = acc;
    }
}

// ---------------- kernel 4: score GEMM (fp16 split, cp.async, frag-B) --------
#define XBUF 16384
#define SS_OFF 0
#define QBI_B 33792
#define SDB_B 34048
#define SCORE_SMEM 34816

// swizzled fp32 x-tile accessor: pair index p (0..15) within a 128B row
__device__ __forceinline__ float2 xs_ld(const char* base, int row, int p) {
    return *(const float2*)(base + row * 128 + ((p ^ ((row & 7) << 1)) << 3));
}

__global__ void __launch_bounds__(128, 2) k_score_tc(const float* __restrict__ x) {
    extern __shared__ char smem[];
    int tid = threadIdx.x, w = tid >> 5, l = tid & 31;
    int b = blockIdx.x >> 5, tile = blockIdx.x & 31;
    int n0 = tile << 7;
    const char* xg = (const char*)(x + ((size_t)(b * N + n0)) * D);

    float acc[2][8][4] = {};

    auto issue = [&](int c) {
        char* bs = smem + (c & 1) * XBUF;
#pragma unroll
        for (int i = 0; i < 8; i++) {
            int row = w * 32 + i * 4 + (l >> 3);
            int jj = l & 7;
            cp_async16(bs + row * 128 + ((jj ^ (row & 7)) << 4),
                       xg + (size_t)row * 4096 + c * 128 + jj * 16);
        }
    };

    issue(0); CP_COMMIT();

    for (int c = 0; c < 32; c++) {
        if (c < 31) { issue(c + 1); CP_COMMIT(); CP_WAIT(1); }
        else        { CP_WAIT(0); }
        __syncthreads();
        const char* xb = smem + (c & 1) * XBUF;
        const uint2* gb = g_Bfrag + (size_t)c * 1024;

#pragma unroll
        for (int s = 0; s < 2; s++) {
            uint32_t a0[2][4], a1[2][4];
#pragma unroll
            for (int mt = 0; mt < 2; mt++) {
                int r = w * 32 + mt * 16 + (l >> 2);
                int p = s * 8 + (l & 3);
                float2 A0 = xs_ld(xb, r, p);
                float2 A1 = xs_ld(xb, r + 8, p);
                float2 A2 = xs_ld(xb, r, p + 4);
                float2 A3 = xs_ld(xb, r + 8, p + 4);
                a0[mt][0] = pack_h2(A0.x, A0.y);
                a0[mt][1] = pack_h2(A1.x, A1.y);
                a0[mt][2] = pack_h2(A2.x, A2.y);
                a0[mt][3] = pack_h2(A3.x, A3.y);
                float2 c0 = unpack_h2(a0[mt][0]), c1 = unpack_h2(a0[mt][1]);
                float2 c2 = unpack_h2(a0[mt][2]), c3 = unpack_h2(a0[mt][3]);
                a1[mt][0] = pack_h2(A0.x - c0.x, A0.y - c0.y);
                a1[mt][1] = pack_h2(A1.x - c1.x, A1.y - c1.y);
                a1[mt][2] = pack_h2(A2.x - c2.x, A2.y - c2.y);
                a1[mt][3] = pack_h2(A3.x - c3.x, A3.y - c3.y);
            }
#pragma unroll
            for (int j = 0; j < 8; j++) {
                uint2 b0 = __ldg(gb + ((s * 8 + j) * 2 + 0) * 32 + l);
                uint2 b1 = __ldg(gb + ((s * 8 + j) * 2 + 1) * 32 + l);
#pragma unroll
                for (int mt = 0; mt < 2; mt++) {
                    mma_f16(acc[mt][j], a0[mt], b0.x, b0.y);
                    mma_f16(acc[mt][j], a0[mt], b1.x, b1.y);
                    mma_f16(acc[mt][j], a1[mt], b0.x, b0.y);
                }
            }
        }
        __syncthreads();
    }

    // ---- epilogue ----
    float* sS   = (float*)(smem + SS_OFF);     // [64 q][132]
    float* sqbi = (float*)(smem + QBI_B);
    float* sdb  = (float*)(smem + SDB_B);
    if (tid < 64) sqbi[tid] = g_qbi[tid];
    sdb[tid] = g_dbias[b * N + n0 + tid];
    __syncthreads();

#pragma unroll
    for (int mt = 0; mt < 2; mt++) {
        int rb = w * 32 + mt * 16 + (l >> 2);
        float d0 = sdb[rb], d1 = sdb[rb + 8];
#pragma unroll
        for (int j = 0; j < 8; j++) {
            int q0 = j * 8 + (l & 3) * 2;
            float t0 = sqbi[q0], t1 = sqbi[q0 + 1];
            sS[q0 * 132 + rb]           = fmaf(acc[mt][j][0], 0.03125f, t0 + d0);
            sS[(q0 + 1) * 132 + rb]     = fmaf(acc[mt][j][1], 0.03125f, t1 + d0);
            sS[q0 * 132 + rb + 8]       = fmaf(acc[mt][j][2], 0.03125f, t0 + d1);
            sS[(q0 + 1) * 132 + rb + 8] = fmaf(acc[mt][j][3], 0.03125f, t1 + d1);
        }
    }
    __syncthreads();

    // coalesced store: warp w writes queries [w*16, w*16+16)
#pragma unroll
    for (int qi = 0; qi < 16; qi++) {
        int q = w * 16 + qi;
        float4 v = *(float4*)(sS + q * 132 + l * 4);
        *(float4*)(g_S + (((size_t)(b * NQ + q)) << 12) + n0 + l * 4) = v;
    }

    // per-tile softmax partials: thread t -> (q = t>>1, half = t&1)
    {
        int q = tid >> 1, half = tid & 1;
        const float* row = sS + q * 132 + half * 64;
        float m = -1e30f;
#pragma unroll
        for (int i = 0; i < 64; i++) m = fmaxf(m, row[i]);
        float mo = __shfl_xor_sync(~0u, m, 1);
        float M = fmaxf(m, mo);
        float z = 0.f;
#pragma unroll
        for (int i = 0; i < 64; i++) z += expf(row[i] - M);
        z += __shfl_xor_sync(~0u, z, 1);
        if (half == 0) {
            g_pmax[(b * 32 + tile) * NQ + q] = M;
            g_psum[(b * 32 + tile) * NQ + q] = z;
        }
    }
}

// ---------------- kernel 5: combine partials -> c ----------------------------
__global__ void k_combine() {
    int t = blockIdx.x * 256 + threadIdx.x;
    int b = t >> 6, q = t & 63;
    float M = -1e30f;
#pragma unroll 8
    for (int tl = 0; tl < 32; tl++)
        M = fmaxf(M, g_pmax[(b * 32 + tl) * NQ + q]);
    float Z = 0.f;
#pragma unroll 8
    for (int tl = 0; tl < 32; tl++)
        Z += g_psum[(b * 32 + tl) * NQ + q] * expf(g_pmax[(b * 32 + tl) * NQ + q] - M);
    g_c[b * NQ + q] = M + logf(Z);
}

// ---------------- kernel 6: importance (log-domain) --------------------------
__global__ void k_imp() {
    __shared__ float sc[NQ];
    int t = blockIdx.x * 256 + threadIdx.x;
    int b = t >> 12;
    if (threadIdx.x < NQ) sc[threadIdx.x] = g_c[b * NQ + threadIdx.x];
    __syncthreads();
    int n = t & (N - 1);
    const float* Sp = g_S + ((size_t)(b * NQ) << 12) + n;
    float best = -1e30f;
#pragma unroll 8
    for (int q = 0; q < NQ; q++) best = fmaxf(best, Sp[(size_t)q << 12] - sc[q]);
    g_imp[t] = best;
}

// ---------------- kernel 7: exact rank (stable top-k) ------------------------
__global__ void __launch_bounds__(256) k_rank() {
    __shared__ unsigned long long key[N];
    int b   = blockIdx.x >> 4;
    int seg = blockIdx.x & 15;
    int tid = threadIdx.x;
    for (int i = tid; i < N; i += 256) {
        unsigned u = __float_as_uint(g_imp[b * N + i]);
        u ^= ((unsigned)(((int)u) >> 31)) | 0x80000000u;
        key[i] = ((unsigned long long)u << 12) | (unsigned)(N - 1 - i);
    }
    __syncthreads();
    int i = seg * 256 + tid;
    unsigned long long ki = key[i];
    int r = 0;
#pragma unroll 8
    for (int j = 0; j < N; j++) r += (key[j] > ki);
    g_flag[b * N + i] = (r < TOPK) ? 1 : 0;
}

// ---------------- kernel 8: compact selected indices -------------------------
__global__ void k_compact() {
    __shared__ unsigned words[N / 32];
    __shared__ int pre[N / 32];
    int b   = blockIdx.x;
    int tid = threadIdx.x;
#pragma unroll
    for (int cc = 0; cc < N / 1024; cc++) {
        int gi = cc * 1024 + tid;
        unsigned bal = __ballot_sync(~0u, g_flag[b * N + gi]);
        if ((tid & 31) == 0) words[gi >> 5] = bal;
    }
    __syncthreads();
    if (tid == 0) {
        int s = 0;
        for (int w = 0; w < N / 32; w++) { pre[w] = s; s += __popc(words[w]); }
    }
    __syncthreads();
#pragma unroll
    for (int cc = 0; cc < N / 1024; cc++) {
        int gi = cc * 1024 + tid;
        unsigned w = words[gi >> 5];
        if ((w >> (gi & 31)) & 1u) {
            int slot = pre[gi >> 5] + __popc(w & ((1u << (gi & 31)) - 1u));
            g_idx[b * TOPK + slot] = gi;
        }
    }
}

// ---------------- kernel 9: gather selected rows -----------------------------
__global__ void k_gather(const float* __restrict__ x, float* __restrict__ out) {
    int row = blockIdx.x;
    int b   = row >> 10;
    int i   = g_idx[row];
    const float4* src = (const float4*)(x + ((size_t)(b * N + i)) * D);
    float4* dst = (float4*)(out + (size_t)row * D);
    dst[threadIdx.x] = src[threadIdx.x];
}

// ---------------- launch -----------------------------------------------------
extern "C" void kernel_launch(void* const* d_in, const int* in_sizes, int n_in,
                              void* d_out, int out_size) {
    const float* tf   = (const float*)d_in[0];
    const float* dens = (const float*)d_in[1];
    const float* qe   = (const float*)d_in[2];
    const float* kw   = (const float*)d_in[3];
    const float* kb   = (const float*)d_in[4];
    const float* w1   = (const float*)d_in[5];
    const float* b1   = (const float*)d_in[6];
    const float* w2   = (const float*)d_in[7];
    const float* b2   = (const float*)d_in[8];
    float* out = (float*)d_out;

    cudaFuncSetAttribute(k_score_tc, cudaFuncAttributeMaxDynamicSharedMemorySize, SCORE_SMEM);

    k_init<<<2, 256>>>(qe, kb, b2, w1, b1, w2);
    k_qw<<<128, 256>>>(qe, kw);
    k_bfrag<<<128, 256>>>();
    k_db<<<128, 256>>>(dens, w1, b1, w2);
    k_score_tc<<<256, 128, SCORE_SMEM>>>(tf);
    k_combine<<<2, 256>>>();
    k_imp<<<B * N / 256, 256>>>();
    k_rank<<<B * 16, 256>>>();
    k_compact<<<B, 1024>>>();
    k_gather<<<B * TOPK, 256>>>(tf, out);
}

// round 7
// speedup vs baseline: 1.3038x; 1.3038x over previous
#include <cuda_runtime.h>
#include <cuda_fp16.h>
#include <cstdint>

#define B 8
#define N 4096
#define D 1024
#define H 1024
#define NQ 64
#define H2 2048
#define TOPK 1024

// ---------------- scratch ----------------------------------------------------
__device__ __align__(16) float g_QWf[NQ * D];   // fp32 QW [q][d]
__device__ float g_qbi[NQ];                     // qb/32 + b2
__device__ float g_dbias[B * N];
__device__ __align__(16) float g_St[B * N * NQ];  // scores token-major [b][n][q]
__device__ float g_pmax[B * 32 * NQ];
__device__ float g_psum[B * 32 * NQ];
__device__ float g_imp[B * N];
__device__ int   g_flag[B * N];
__device__ int   g_idx[B * TOPK];
__device__ float g_C1, g_C2;
__device__ int   g_bz;

// ---------------- helpers ----------------------------------------------------
__device__ __forceinline__ uint32_t pack_h2(float a, float b) {
    __half2 h = __floats2half2_rn(a, b);
    return *reinterpret_cast<uint32_t*>(&h);
}
__device__ __forceinline__ float2 unpack_h2(uint32_t u) {
    __half2 h = *reinterpret_cast<__half2*>(&u);
    return __half22float2(h);
}
__device__ __forceinline__ void mma_f16(float* d, const uint32_t* a, uint32_t b0, uint32_t b1) {
    asm volatile("mma.sync.aligned.m16n8k16.row.col.f32.f16.f16.f32 "
        "{%0,%1,%2,%3}, {%4,%5,%6,%7}, {%8,%9}, {%0,%1,%2,%3};"
        : "+f"(d[0]), "+f"(d[1]), "+f"(d[2]), "+f"(d[3])
        : "r"(a[0]), "r"(a[1]), "r"(a[2]), "r"(a[3]), "r"(b0), "r"(b1));
}
__device__ __forceinline__ void cp_async16(void* dst_smem, const void* src) {
    uint32_t d;
    asm("{ .reg .u64 t; cvta.to.shared.u64 t, %1; cvt.u32.u64 %0, t; }" : "=r"(d) : "l"(dst_smem));
    asm volatile("cp.async.cg.shared.global [%0], [%1], 16;" :: "r"(d), "l"(src) : "memory");
}
#define CP_COMMIT() asm volatile("cp.async.commit_group;" ::: "memory")
#define CP_WAIT(n)  asm volatile("cp.async.wait_group %0;" :: "n"(n) : "memory")

// ---------------- kernel 0: init (qbi + density consts) ----------------------
__global__ void k_init(const float* __restrict__ qe, const float* __restrict__ kb,
                       const float* __restrict__ b2, const float* __restrict__ w1,
                       const float* __restrict__ b1, const float* __restrict__ w2) {
    int tid = threadIdx.x;
    if (blockIdx.x == 0) {
        int w = tid >> 5, l = tid & 31;
        float b2v = b2[0];
#pragma unroll
        for (int qi = 0; qi < 8; qi++) {
            int q = w * 8 + qi;
            float acc = 0.f;
#pragma unroll
            for (int k = 0; k < 32; k++)
                acc = fmaf(qe[(size_t)q * H + k * 32 + l], kb[k * 32 + l], acc);
#pragma unroll
            for (int o = 16; o; o >>= 1) acc += __shfl_xor_sync(~0u, acc, o);
            if (l == 0) g_qbi[q] = acc * 0.03125f + b2v;
        }
    } else {
        __shared__ float r1[256], r2[256];
        __shared__ int rz[256];
        float c1 = 0.f, c2 = 0.f; int bz = 1;
        for (int j = tid; j < H2; j += 256) {
            float a = w1[j], c = w2[j];
            if (a > 0.f) c1 += a * c; else c2 += a * c;
            if (b1[j] != 0.f) bz = 0;
        }
        r1[tid] = c1; r2[tid] = c2; rz[tid] = bz;
        __syncthreads();
        for (int o = 128; o; o >>= 1) {
            if (tid < o) { r1[tid] += r1[tid + o]; r2[tid] += r2[tid + o]; rz[tid] &= rz[tid + o]; }
            __syncthreads();
        }
        if (tid == 0) { g_C1 = r1[0]; g_C2 = r2[0]; g_bz = rz[0]; }
    }
}

// ---------------- kernel 1: QW GEMM (fp32) -----------------------------------
__global__ void __launch_bounds__(256) k_qw(const float* __restrict__ qe,
                                            const float* __restrict__ kw) {
    __shared__ float skw[8][68];
    __shared__ float sqt[64][65];
    int d0 = blockIdx.x * 8;
    int tid = threadIdx.x;
    int q = tid & 63, dp = tid >> 6;
    float acc0 = 0.f, acc1 = 0.f;
    for (int k0 = 0; k0 < H; k0 += 64) {
#pragma unroll
        for (int r = 0; r < 2; r++) {
            int idx = tid + 256 * r;
            skw[idx >> 6][idx & 63] = kw[(size_t)(d0 + (idx >> 6)) * H + k0 + (idx & 63)];
        }
#pragma unroll
        for (int r = 0; r < 4; r++) {
            int idx = tid + 256 * r;
            int row = idx >> 4, c4 = (idx & 15) * 4;
            float4 v = *(const float4*)(qe + (size_t)row * H + k0 + c4);
            sqt[c4 + 0][row] = v.x; sqt[c4 + 1][row] = v.y;
            sqt[c4 + 2][row] = v.z; sqt[c4 + 3][row] = v.w;
        }
        __syncthreads();
#pragma unroll 8
        for (int k = 0; k < 64; k++) {
            float qv = sqt[k][q];
            acc0 = fmaf(skw[dp][k], qv, acc0);
            acc1 = fmaf(skw[dp + 4][k], qv, acc1);
        }
        __syncthreads();
    }
    g_QWf[(size_t)q * D + d0 + dp] = acc0;
    g_QWf[(size_t)q * D + d0 + dp + 4] = acc1;
}

// ---------------- kernel 2: density bias -------------------------------------
__global__ void k_db(const float* __restrict__ dens, const float* __restrict__ w1,
                     const float* __restrict__ b1, const float* __restrict__ w2) {
    int t = blockIdx.x * 256 + threadIdx.x;
    float d = dens[t];
    if (g_bz) {
        g_dbias[t] = d * (d >= 0.f ? g_C1 : g_C2);
    } else {
        float acc = 0.f;
        for (int j = 0; j < H2; j++)
            acc = fmaf(fmaxf(fmaf(d, w1[j], b1[j]), 0.f), w2[j], acc);
        g_dbias[t] = acc;
    }
}

// ---------------- kernel 3: score GEMM (fp16 split, fp32 smem staging) -------
// float offsets in dynamic smem
#define XB0 0
#define XB1 5120
#define BB0 10240
#define BB1 12800
#define PM_OFF 15360
#define PZ_OFF 15616
#define QBI_OFF 15872
#define SDB_OFF 15936
#define SCORE_SMEM 64256     // 16064 floats

__global__ void __launch_bounds__(256, 2) k_score_tc(const float* __restrict__ x) {
    extern __shared__ float sm[];
    int tid = threadIdx.x, w = tid >> 5, l = tid & 31;
    int b = blockIdx.x >> 5, tile = blockIdx.x & 31;
    int n0 = tile << 7;
    int wm = w & 3, wn = w >> 2;
    const char* xg = (const char*)(x + ((size_t)(b * N + n0)) * D);
    const char* bg = (const char*)g_QWf;

    if (tid < 64) sm[QBI_OFF + tid] = g_qbi[tid];
    if (tid < 128) sm[SDB_OFF + tid] = g_dbias[b * N + n0 + tid];

    float acc[2][4][4] = {};

    int xrow = tid >> 1, xj = (tid & 1) * 4;
    int bq = tid >> 2, bj = (tid & 3) * 2;

    auto issue = [&](int c) {
        float* xb = sm + ((c & 1) ? XB1 : XB0);
        float* bb = sm + ((c & 1) ? BB1 : BB0);
#pragma unroll
        for (int i = 0; i < 4; i++)
            cp_async16(xb + xrow * 40 + (xj + i) * 4,
                       xg + (size_t)xrow * 4096 + (size_t)c * 128 + (xj + i) * 16);
#pragma unroll
        for (int i = 0; i < 2; i++)
            cp_async16(bb + bq * 40 + (bj + i) * 4,
                       bg + (size_t)bq * 4096 + (size_t)c * 128 + (bj + i) * 16);
    };

    issue(0); CP_COMMIT();

    for (int c = 0; c < 32; c++) {
        if (c < 31) { issue(c + 1); CP_COMMIT(); CP_WAIT(1); }
        else        { CP_WAIT(0); }
        __syncthreads();
        const float* xb = sm + ((c & 1) ? XB1 : XB0);
        const float* bb = sm + ((c & 1) ? BB1 : BB0);

#pragma unroll
        for (int s = 0; s < 2; s++) {
            int kc = s * 16 + (l & 3) * 2;
            uint32_t b0f[4][2], b1f[4][2];
#pragma unroll
            for (int nt = 0; nt < 4; nt++) {
                int q = wn * 32 + nt * 8 + (l >> 2);
                float2 e0 = *(const float2*)(bb + q * 40 + kc);
                float2 e1 = *(const float2*)(bb + q * 40 + kc + 8);
                b0f[nt][0] = pack_h2(e0.x, e0.y);
                b0f[nt][1] = pack_h2(e1.x, e1.y);
                float2 c0 = unpack_h2(b0f[nt][0]), c1 = unpack_h2(b0f[nt][1]);
                b1f[nt][0] = pack_h2(e0.x - c0.x, e0.y - c0.y);
                b1f[nt][1] = pack_h2(e1.x - c1.x, e1.y - c1.y);
            }
#pragma unroll
            for (int mt = 0; mt < 2; mt++) {
                int r = wm * 32 + mt * 16 + (l >> 2);
                float2 A0 = *(const float2*)(xb + r * 40 + kc);
                float2 A1 = *(const float2*)(xb + (r + 8) * 40 + kc);
                float2 A2 = *(const float2*)(xb + r * 40 + kc + 8);
                float2 A3 = *(const float2*)(xb + (r + 8) * 40 + kc + 8);
                uint32_t a0[4], a1[4];
                a0[0] = pack_h2(A0.x, A0.y); a0[1] = pack_h2(A1.x, A1.y);
                a0[2] = pack_h2(A2.x, A2.y); a0[3] = pack_h2(A3.x, A3.y);
                float2 c0 = unpack_h2(a0[0]), c1 = unpack_h2(a0[1]);
                float2 c2 = unpack_h2(a0[2]), c3 = unpack_h2(a0[3]);
                a1[0] = pack_h2(A0.x - c0.x, A0.y - c0.y);
                a1[1] = pack_h2(A1.x - c1.x, A1.y - c1.y);
                a1[2] = pack_h2(A2.x - c2.x, A2.y - c2.y);
                a1[3] = pack_h2(A3.x - c3.x, A3.y - c3.y);
#pragma unroll
                for (int nt = 0; nt < 4; nt++) {
                    mma_f16(acc[mt][nt], a0, b0f[nt][0], b0f[nt][1]);
                    mma_f16(acc[mt][nt], a0, b1f[nt][0], b1f[nt][1]);
                    mma_f16(acc[mt][nt], a1, b0f[nt][0], b0f[nt][1]);
                }
            }
        }
        __syncthreads();
    }

    // ---- epilogue: bias + stage token-major + store + softmax partials ------
    float* sS = sm;                         // [128 tok][68]
#pragma unroll
    for (int mt = 0; mt < 2; mt++) {
        int r = wm * 32 + mt * 16 + (l >> 2);
        float d0 = sm[SDB_OFF + r], d1 = sm[SDB_OFF + r + 8];
#pragma unroll
        for (int nt = 0; nt < 4; nt++) {
            int q = wn * 32 + nt * 8 + (l & 3) * 2;
            float t0 = sm[QBI_OFF + q], t1 = sm[QBI_OFF + q + 1];
            sS[r * 68 + q]           = fmaf(acc[mt][nt][0], 0.03125f, t0 + d0);
            sS[r * 68 + q + 1]       = fmaf(acc[mt][nt][1], 0.03125f, t1 + d0);
            sS[(r + 8) * 68 + q]     = fmaf(acc[mt][nt][2], 0.03125f, t0 + d1);
            sS[(r + 8) * 68 + q + 1] = fmaf(acc[mt][nt][3], 0.03125f, t1 + d1);
        }
    }
    __syncthreads();

    {   // token-major coalesced store
        int tok = tid >> 1, h = tid & 1;
        float* dst = g_St + ((size_t)(b * N + n0 + tok)) * 64 + h * 32;
        const float* src = sS + tok * 68 + h * 32;
#pragma unroll
        for (int i = 0; i < 8; i++)
            *(float4*)(dst + i * 4) = *(const float4*)(src + i * 4);
    }

    {   // per-tile softmax partials
        int q = tid & 63, grp = tid >> 6;
        const float* col = sS + (grp * 32) * 68 + q;
        float m = -1e30f;
#pragma unroll
        for (int i = 0; i < 32; i++) m = fmaxf(m, col[i * 68]);
        float z = 0.f;
#pragma unroll
        for (int i = 0; i < 32; i++) z += expf(col[i * 68] - m);
        sm[PM_OFF + grp * 64 + q] = m;
        sm[PZ_OFF + grp * 64 + q] = z;
    }
    __syncthreads();
    if (tid < 64) {
        float M = sm[PM_OFF + tid];
        M = fmaxf(M, sm[PM_OFF + 64 + tid]);
        M = fmaxf(M, sm[PM_OFF + 128 + tid]);
        M = fmaxf(M, sm[PM_OFF + 192 + tid]);
        float Z = 0.f;
#pragma unroll
        for (int g = 0; g < 4; g++)
            Z += sm[PZ_OFF + g * 64 + tid] * expf(sm[PM_OFF + g * 64 + tid] - M);
        g_pmax[(b * 32 + tile) * NQ + tid] = M;
        g_psum[(b * 32 + tile) * NQ + tid] = Z;
    }
}

// ---------------- kernel 4: importance (fused logsumexp combine) -------------
__global__ void k_imp2() {
    __shared__ float sc[NQ];
    int blk = blockIdx.x, tid = threadIdx.x;
    int b = blk >> 4;
    if (tid < 64) {
        float M = -1e30f;
#pragma unroll 8
        for (int tl = 0; tl < 32; tl++)
            M = fmaxf(M, g_pmax[(b * 32 + tl) * NQ + tid]);
        float Z = 0.f;
#pragma unroll 8
        for (int tl = 0; tl < 32; tl++)
            Z += g_psum[(b * 32 + tl) * NQ + tid] * expf(g_pmax[(b * 32 + tl) * NQ + tid] - M);
        sc[tid] = M + logf(Z);
    }
    __syncthreads();
    int n = (blk & 15) * 256 + tid;
    const float4* row = (const float4*)(g_St + ((size_t)(b * N + n)) * 64);
    float best = -1e30f;
#pragma unroll
    for (int i = 0; i < 16; i++) {
        float4 v = row[i];
        int q = i * 4;
        best = fmaxf(best, fmaxf(fmaxf(v.x - sc[q], v.y - sc[q + 1]),
                                 fmaxf(v.z - sc[q + 2], v.w - sc[q + 3])));
    }
    g_imp[b * N + n] = best;
}

// ---------------- kernel 5: exact rank (stable top-k) ------------------------
__global__ void __launch_bounds__(256) k_rank() {
    __shared__ unsigned long long key[N];
    int b   = blockIdx.x >> 4;
    int seg = blockIdx.x & 15;
    int tid = threadIdx.x;
    for (int i = tid; i < N; i += 256) {
        unsigned u = __float_as_uint(g_imp[b * N + i]);
        u ^= ((unsigned)(((int)u) >> 31)) | 0x80000000u;
        key[i] = ((unsigned long long)u << 12) | (unsigned)(N - 1 - i);
    }
    __syncthreads();
    int i = seg * 256 + tid;
    unsigned long long ki = key[i];
    int r = 0;
#pragma unroll 8
    for (int j = 0; j < N; j++) r += (key[j] > ki);
    g_flag[b * N + i] = (r < TOPK) ? 1 : 0;
}

// ---------------- kernel 6: compact selected indices -------------------------
__global__ void k_compact() {
    __shared__ unsigned words[N / 32];
    __shared__ int pre[N / 32];
    int b   = blockIdx.x;
    int tid = threadIdx.x;
#pragma unroll
    for (int cc = 0; cc < N / 1024; cc++) {
        int gi = cc * 1024 + tid;
        unsigned bal = __ballot_sync(~0u, g_flag[b * N + gi]);
        if ((tid & 31) == 0) words[gi >> 5] = bal;
    }
    __syncthreads();
    if (tid == 0) {
        int s = 0;
        for (int w = 0; w < N / 32; w++) { pre[w] = s; s += __popc(words[w]); }
    }
    __syncthreads();
#pragma unroll
    for (int cc = 0; cc < N / 1024; cc++) {
        int gi = cc * 1024 + tid;
        unsigned w = words[gi >> 5];
        if ((w >> (gi & 31)) & 1u) {
            int slot = pre[gi >> 5] + __popc(w & ((1u << (gi & 31)) - 1u));
            g_idx[b * TOPK + slot] = gi;
        }
    }
}

// ---------------- kernel 7: gather selected rows -----------------------------
__global__ void k_gather(const float* __restrict__ x, float* __restrict__ out) {
    int row = blockIdx.x;
    int b   = row >> 10;
    int i   = g_idx[row];
    const float4* src = (const float4*)(x + ((size_t)(b * N + i)) * D);
    float4* dst = (float4*)(out + (size_t)row * D);
    dst[threadIdx.x] = src[threadIdx.x];
}

// ---------------- launch -----------------------------------------------------
extern "C" void kernel_launch(void* const* d_in, const int* in_sizes, int n_in,
                              void* d_out, int out_size) {
    const float* tf   = (const float*)d_in[0];
    const float* dens = (const float*)d_in[1];
    const float* qe   = (const float*)d_in[2];
    const float* kw   = (const float*)d_in[3];
    const float* kb   = (const float*)d_in[4];
    const float* w1   = (const float*)d_in[5];
    const float* b1   = (const float*)d_in[6];
    const float* w2   = (const float*)d_in[7];
    const float* b2   = (const float*)d_in[8];
    float* out = (float*)d_out;

    cudaFuncSetAttribute(k_score_tc, cudaFuncAttributeMaxDynamicSharedMemorySize, SCORE_SMEM);

    k_init<<<2, 256>>>(qe, kb, b2, w1, b1, w2);
    k_qw<<<128, 256>>>(qe, kw);
    k_db<<<128, 256>>>(dens, w1, b1, w2);
    k_score_tc<<<256, 256, SCORE_SMEM>>>(tf);
    k_imp2<<<B * N / 256, 256>>>();
    k_rank<<<B * 16, 256>>>();
    k_compact<<<B, 1024>>>();
    k_gather<<<B * TOPK, 256>>>(tf, out);
}

// round 9
// speedup vs baseline: 1.5542x; 1.1921x over previous
#include <cuda_runtime.h>
#include <cuda_fp16.h>
#include <cstdint>

#define B 8
#define N 4096
#define D 1024
#define H 1024
#define NQ 64
#define H2 2048
#define TOPK 1024

// ---------------- scratch ----------------------------------------------------
__device__ __align__(16) float g_QWf[NQ * D];     // fp32 QW [q][d]
__device__ __align__(16) uint2 g_Bfrag[32768];    // fp16 fragment-ordered B
__device__ float g_qbi[NQ];                       // qb/32 + b2
__device__ __align__(16) float g_St[B * N * NQ];  // scores token-major
__device__ float g_pmax[B * 32 * NQ];
__device__ float g_psum[B * 32 * NQ];
__device__ float g_imp[B * N];
__device__ int   g_flag[B * N];
__device__ int   g_idx[B * TOPK];
__device__ float g_C1, g_C2;
__device__ int   g_bz;

// ---------------- helpers ----------------------------------------------------
__device__ __forceinline__ uint32_t pack_h2(float a, float b) {
    __half2 h = __floats2half2_rn(a, b);
    return *reinterpret_cast<uint32_t*>(&h);
}
__device__ __forceinline__ float2 unpack_h2(uint32_t u) {
    __half2 h = *reinterpret_cast<__half2*>(&u);
    return __half22float2(h);
}
__device__ __forceinline__ void mma_f16(float* d, const uint32_t* a, uint32_t b0, uint32_t b1) {
    asm volatile("mma.sync.aligned.m16n8k16.row.col.f32.f16.f16.f32 "
        "{%0,%1,%2,%3}, {%4,%5,%6,%7}, {%8,%9}, {%0,%1,%2,%3};"
        : "+f"(d[0]), "+f"(d[1]), "+f"(d[2]), "+f"(d[3])
        : "r"(a[0]), "r"(a[1]), "r"(a[2]), "r"(a[3]), "r"(b0), "r"(b1));
}
__device__ __forceinline__ void cp_async16(void* dst_smem, const void* src) {
    uint32_t d;
    asm("{ .reg .u64 t; cvta.to.shared.u64 t, %1; cvt.u32.u64 %0, t; }" : "=r"(d) : "l"(dst_smem));
    asm volatile("cp.async.cg.shared.global [%0], [%1], 16;" :: "r"(d), "l"(src) : "memory");
}
#define CP_COMMIT() asm volatile("cp.async.commit_group;" ::: "memory")
#define CP_WAIT(n)  asm volatile("cp.async.wait_group %0;" :: "n"(n) : "memory")

// ---------------- kernel 0: prep (QW GEMM + qbi + density consts) ------------
__global__ void __launch_bounds__(256) k_prep(const float* __restrict__ qe,
                                              const float* __restrict__ kw,
                                              const float* __restrict__ kb,
                                              const float* __restrict__ b2,
                                              const float* __restrict__ w1,
                                              const float* __restrict__ b1,
                                              const float* __restrict__ w2) {
    int tid = threadIdx.x;
    int bid = blockIdx.x;
    if (bid < 128) {
        __shared__ float skw[8][68];
        __shared__ float sqt[64][65];
        int d0 = bid * 8;
        int q = tid & 63, dp = tid >> 6;
        float acc0 = 0.f, acc1 = 0.f;
        for (int k0 = 0; k0 < H; k0 += 64) {
#pragma unroll
            for (int r = 0; r < 2; r++) {
                int idx = tid + 256 * r;
                skw[idx >> 6][idx & 63] = kw[(size_t)(d0 + (idx >> 6)) * H + k0 + (idx & 63)];
            }
#pragma unroll
            for (int r = 0; r < 4; r++) {
                int idx = tid + 256 * r;
                int row = idx >> 4, c4 = (idx & 15) * 4;
                float4 v = *(const float4*)(qe + (size_t)row * H + k0 + c4);
                sqt[c4 + 0][row] = v.x; sqt[c4 + 1][row] = v.y;
                sqt[c4 + 2][row] = v.z; sqt[c4 + 3][row] = v.w;
            }
            __syncthreads();
#pragma unroll 8
            for (int k = 0; k < 64; k++) {
                float qv = sqt[k][q];
                acc0 = fmaf(skw[dp][k], qv, acc0);
                acc1 = fmaf(skw[dp + 4][k], qv, acc1);
            }
            __syncthreads();
        }
        g_QWf[(size_t)q * D + d0 + dp] = acc0;
        g_QWf[(size_t)q * D + d0 + dp + 4] = acc1;
    } else if (bid == 128) {
        int w = tid >> 5, l = tid & 31;
        float b2v = b2[0];
#pragma unroll
        for (int qi = 0; qi < 8; qi++) {
            int q = w * 8 + qi;
            float acc = 0.f;
#pragma unroll
            for (int k = 0; k < 32; k++)
                acc = fmaf(qe[(size_t)q * H + k * 32 + l], kb[k * 32 + l], acc);
#pragma unroll
            for (int o = 16; o; o >>= 1) acc += __shfl_xor_sync(~0u, acc, o);
            if (l == 0) g_qbi[q] = acc * 0.03125f + b2v;
        }
    } else {
        __shared__ float r1[256], r2[256];
        __shared__ int rz[256];
        float c1 = 0.f, c2 = 0.f; int bz = 1;
        for (int j = tid; j < H2; j += 256) {
            float a = w1[j], c = w2[j];
            if (a > 0.f) c1 += a * c; else c2 += a * c;
            if (b1[j] != 0.f) bz = 0;
        }
        r1[tid] = c1; r2[tid] = c2; rz[tid] = bz;
        __syncthreads();
        for (int o = 128; o; o >>= 1) {
            if (tid < o) { r1[tid] += r1[tid + o]; r2[tid] += r2[tid + o]; rz[tid] &= rz[tid + o]; }
            __syncthreads();
        }
        if (tid == 0) { g_C1 = r1[0]; g_C2 = r2[0]; g_bz = rz[0]; }
    }
}

// ---------------- kernel 1: pack B into fp16 fragment order ------------------
__global__ void k_bfrag() {
    int t = blockIdx.x * 256 + threadIdx.x;   // < 32768
    int lane = t & 31, pl = (t >> 5) & 1, j = (t >> 6) & 7, s = (t >> 9) & 1, c = t >> 10;
    int q = j * 8 + (lane >> 2);
    int k0 = c * 32 + s * 16 + (lane & 3) * 2;
    const float* w = g_QWf + (size_t)q * D + k0;
    float f0 = w[0], f1 = w[1], f2 = w[8], f3 = w[9];
    uint32_t ha = pack_h2(f0, f1), hb = pack_h2(f2, f3);
    if (pl == 0) {
        g_Bfrag[t] = make_uint2(ha, hb);
    } else {
        float2 ca = unpack_h2(ha), cb = unpack_h2(hb);
        g_Bfrag[t] = make_uint2(pack_h2(f0 - ca.x, f1 - ca.y),
                                pack_h2(f2 - cb.x, f3 - cb.y));
    }
}

// ---------------- kernel 2: score GEMM (3-stage, frag-B, inline dbias) -------
// float offsets in dynamic smem
#define XB(s)  ((s) * 4096)            // 3 X buffers, 128 rows x 32 (swizzled)
#define PM_OFF 9216                    // inside XB region; free after mainloop
#define PZ_OFF 9472
#define BBF(s) (12288 + (s) * 2048)    // 3 B fragment buffers (1024 uint2)
#define SDB_OFF 18432
#define QBI_OFF 18560
#define SCORE_SMEM 74496               // 18624 floats

__global__ void __launch_bounds__(256, 2) k_score_tc(const float* __restrict__ x,
                                                     const float* __restrict__ dens,
                                                     const float* __restrict__ w1,
                                                     const float* __restrict__ b1,
                                                     const float* __restrict__ w2) {
    extern __shared__ float sm[];
    int tid = threadIdx.x, w = tid >> 5, l = tid & 31;
    int b = blockIdx.x >> 5, tile = blockIdx.x & 31;
    int n0 = tile << 7;
    int wm = w & 3, wn = w >> 2;
    const char* xg = (const char*)(x + ((size_t)(b * N + n0)) * D);
    const char* fg = (const char*)g_Bfrag;

    float acc[2][4][4] = {};

    int xrow = tid >> 1;                 // 0..127
    int xc0  = (tid & 1) * 4;            // chunk base 0 or 4

    auto issue = [&](int c) {
        int st = c % 3;
        float* xb = sm + XB(st);
        float* bb = sm + BBF(st);
#pragma unroll
        for (int i = 0; i < 4; i++) {
            int ch = xc0 + i;
            int chs = ch ^ ((xrow & 3) << 1);           // swizzled 16B chunk
            cp_async16(xb + xrow * 32 + chs * 4,
                       xg + (size_t)xrow * 4096 + (size_t)c * 128 + ch * 16);
        }
#pragma unroll
        for (int i = 0; i < 2; i++)
            cp_async16(bb + (tid + i * 256) * 4,
                       fg + (size_t)c * 8192 + (tid + i * 256) * 16);
        CP_COMMIT();
    };

    issue(0);
    issue(1);

    for (int c = 0; c < 32; c++) {
        CP_WAIT(1);
        __syncthreads();
        if (c + 2 < 32) issue(c + 2);
        int st = c % 3;
        const float* xb = sm + XB(st);
        const uint2* bb = (const uint2*)(sm + BBF(st));

#pragma unroll
        for (int s = 0; s < 2; s++) {
            // B fragments from smem (pre-split planes)
            uint2 b0f[4], b1f[4];
#pragma unroll
            for (int nt = 0; nt < 4; nt++) {
                int j = wn * 4 + nt;
                b0f[nt] = bb[((s * 8 + j) * 2 + 0) * 32 + l];
                b1f[nt] = bb[((s * 8 + j) * 2 + 1) * 32 + l];
            }
#pragma unroll
            for (int mt = 0; mt < 2; mt++) {
                int r  = wm * 32 + mt * 16 + (l >> 2);
                int p  = s * 8 + (l & 3);
                int sw0 = (p     ^ ((r & 3) << 2)) * 2;
                int sw2 = ((p+4) ^ ((r & 3) << 2)) * 2;
                int r8 = r + 8;
                int t0 = (p     ^ ((r8 & 3) << 2)) * 2;
                int t2 = ((p+4) ^ ((r8 & 3) << 2)) * 2;
                float2 A0 = *(const float2*)(xb + r  * 32 + sw0);
                float2 A1 = *(const float2*)(xb + r8 * 32 + t0);
                float2 A2 = *(const float2*)(xb + r  * 32 + sw2);
                float2 A3 = *(const float2*)(xb + r8 * 32 + t2);
                uint32_t a0[4], a1[4];
                a0[0] = pack_h2(A0.x, A0.y); a0[1] = pack_h2(A1.x, A1.y);
                a0[2] = pack_h2(A2.x, A2.y); a0[3] = pack_h2(A3.x, A3.y);
                float2 c0 = unpack_h2(a0[0]), c1 = unpack_h2(a0[1]);
                float2 c2 = unpack_h2(a0[2]), c3 = unpack_h2(a0[3]);
                a1[0] = pack_h2(A0.x - c0.x, A0.y - c0.y);
                a1[1] = pack_h2(A1.x - c1.x, A1.y - c1.y);
                a1[2] = pack_h2(A2.x - c2.x, A2.y - c2.y);
                a1[3] = pack_h2(A3.x - c3.x, A3.y - c3.y);
#pragma unroll
                for (int nt = 0; nt < 4; nt++) {
                    mma_f16(acc[mt][nt], a0, b0f[nt].x, b0f[nt].y);
                    mma_f16(acc[mt][nt], a0, b1f[nt].x, b1f[nt].y);
                    mma_f16(acc[mt][nt], a1, b0f[nt].x, b0f[nt].y);
                }
            }
        }
    }
    __syncthreads();

    // ---- inline density bias + qbi ----
    if (tid < 128) {
        float d = dens[b * N + n0 + tid];
        float db;
        if (g_bz) {
            db = d * (d >= 0.f ? g_C1 : g_C2);
        } else {
            db = 0.f;
            for (int j = 0; j < H2; j++)
                db = fmaf(fmaxf(fmaf(d, w1[j], b1[j]), 0.f), w2[j], db);
        }
        sm[SDB_OFF + tid] = db;
    } else if (tid < 192) {
        sm[QBI_OFF + tid - 128] = g_qbi[tid - 128];
    }
    __syncthreads();

    // ---- epilogue: bias + stage token-major + store + softmax partials ------
    float* sS = sm;                         // [128 tok][68] = 8704 floats
#pragma unroll
    for (int mt = 0; mt < 2; mt++) {
        int r = wm * 32 + mt * 16 + (l >> 2);
        float d0 = sm[SDB_OFF + r], d1 = sm[SDB_OFF + r + 8];
#pragma unroll
        for (int nt = 0; nt < 4; nt++) {
            int q = wn * 32 + nt * 8 + (l & 3) * 2;
            float t0 = sm[QBI_OFF + q], t1 = sm[QBI_OFF + q + 1];
            sS[r * 68 + q]           = fmaf(acc[mt][nt][0], 0.03125f, t0 + d0);
            sS[r * 68 + q + 1]       = fmaf(acc[mt][nt][1], 0.03125f, t1 + d0);
            sS[(r + 8) * 68 + q]     = fmaf(acc[mt][nt][2], 0.03125f, t0 + d1);
            sS[(r + 8) * 68 + q + 1] = fmaf(acc[mt][nt][3], 0.03125f, t1 + d1);
        }
    }
    __syncthreads();

    {   // token-major coalesced store
        int tok = tid >> 1, h = tid & 1;
        float* dst = g_St + ((size_t)(b * N + n0 + tok)) * 64 + h * 32;
        const float* src = sS + tok * 68 + h * 32;
#pragma unroll
        for (int i = 0; i < 8; i++)
            *(float4*)(dst + i * 4) = *(const float4*)(src + i * 4);
    }

    {   // per-tile softmax partials (pm/pz live in the dead X-buffer region)
        int q = tid & 63, grp = tid >> 6;
        const float* col = sS + (grp * 32) * 68 + q;
        float m = -1e30f;
#pragma unroll
        for (int i = 0; i < 32; i++) m = fmaxf(m, col[i * 68]);
        float z = 0.f;
#pragma unroll
        for (int i = 0; i < 32; i++) z += expf(col[i * 68] - m);
        sm[PM_OFF + grp * 64 + q] = m;
        sm[PZ_OFF + grp * 64 + q] = z;
    }
    __syncthreads();
    if (tid < 64) {
        const float* pm = sm + PM_OFF;
        const float* pz = sm + PZ_OFF;
        float M = pm[tid];
        M = fmaxf(M, pm[64 + tid]);
        M = fmaxf(M, pm[128 + tid]);
        M = fmaxf(M, pm[192 + tid]);
        float Z = 0.f;
#pragma unroll
        for (int g = 0; g < 4; g++)
            Z += pz[g * 64 + tid] * expf(pm[g * 64 + tid] - M);
        g_pmax[(b * 32 + tile) * NQ + tid] = M;
        g_psum[(b * 32 + tile) * NQ + tid] = Z;
    }
}

// ---------------- kernel 3: importance (fused logsumexp combine) -------------
__global__ void k_imp2() {
    __shared__ float sc[NQ];
    int blk = blockIdx.x, tid = threadIdx.x;
    int b = blk >> 4;
    if (tid < 64) {
        float M = -1e30f;
#pragma unroll 8
        for (int tl = 0; tl < 32; tl++)
            M = fmaxf(M, g_pmax[(b * 32 + tl) * NQ + tid]);
        float Z = 0.f;
#pragma unroll 8
        for (int tl = 0; tl < 32; tl++)
            Z += g_psum[(b * 32 + tl) * NQ + tid] * expf(g_pmax[(b * 32 + tl) * NQ + tid] - M);
        sc[tid] = M + logf(Z);
    }
    __syncthreads();
    int n = (blk & 15) * 256 + tid;
    const float4* row = (const float4*)(g_St + ((size_t)(b * N + n)) * 64);
    float best = -1e30f;
#pragma unroll
    for (int i = 0; i < 16; i++) {
        float4 v = row[i];
        int q = i * 4;
        best = fmaxf(best, fmaxf(fmaxf(v.x - sc[q], v.y - sc[q + 1]),
                                 fmaxf(v.z - sc[q + 2], v.w - sc[q + 3])));
    }
    g_imp[b * N + n] = best;
}

// ---------------- kernel 4: exact rank (stable top-k) ------------------------
__global__ void __launch_bounds__(256) k_rank() {
    __shared__ unsigned long long key[N];
    int b   = blockIdx.x >> 4;
    int seg = blockIdx.x & 15;
    int tid = threadIdx.x;
    for (int i = tid; i < N; i += 256) {
        unsigned u = __float_as_uint(g_imp[b * N + i]);
        u ^= ((unsigned)(((int)u) >> 31)) | 0x80000000u;
        key[i] = ((unsigned long long)u << 12) | (unsigned)(N - 1 - i);
    }
    __syncthreads();
    int i = seg * 256 + tid;
    unsigned long long ki = key[i];
    int r = 0;
#pragma unroll 8
    for (int j = 0; j < N; j++) r += (key[j] > ki);
    g_flag[b * N + i] = (r < TOPK) ? 1 : 0;
}

// ---------------- kernel 5: compact selected indices -------------------------
__global__ void k_compact() {
    __shared__ unsigned words[N / 32];
    __shared__ int pre[N / 32];
    int b   = blockIdx.x;
    int tid = threadIdx.x;
#pragma unroll
    for (int cc = 0; cc < N / 1024; cc++) {
        int gi = cc * 1024 + tid;
        unsigned bal = __ballot_sync(~0u, g_flag[b * N + gi]);
        if ((tid & 31) == 0) words[gi >> 5] = bal;
    }
    __syncthreads();
    if (tid == 0) {
        int s = 0;
        for (int w = 0; w < N / 32; w++) { pre[w] = s; s += __popc(words[w]); }
    }
    __syncthreads();
#pragma unroll
    for (int cc = 0; cc < N / 1024; cc++) {
        int gi = cc * 1024 + tid;
        unsigned w = words[gi >> 5];
        if ((w >> (gi & 31)) & 1u) {
            int slot = pre[gi >> 5] + __popc(w & ((1u << (gi & 31)) - 1u));
            g_idx[b * TOPK + slot] = gi;
        }
    }
}

// ---------------- kernel 6: gather selected rows -----------------------------
__global__ void k_gather(const float* __restrict__ x, float* __restrict__ out) {
    int row = blockIdx.x;
    int b   = row >> 10;
    int i   = g_idx[row];
    const float4* src = (const float4*)(x + ((size_t)(b * N + i)) * D);
    float4* dst = (float4*)(out + (size_t)row * D);
    dst[threadIdx.x] = src[threadIdx.x];
}

// ---------------- launch -----------------------------------------------------
extern "C" void kernel_launch(void* const* d_in, const int* in_sizes, int n_in,
                              void* d_out, int out_size) {
    const float* tf   = (const float*)d_in[0];
    const float* dens = (const float*)d_in[1];
    const float* qe   = (const float*)d_in[2];
    const float* kw   = (const float*)d_in[3];
    const float* kb   = (const float*)d_in[4];
    const float* w1   = (const float*)d_in[5];
    const float* b1   = (const float*)d_in[6];
    const float* w2   = (const float*)d_in[7];
    const float* b2   = (const float*)d_in[8];
    float* out = (float*)d_out;

    cudaFuncSetAttribute(k_score_tc, cudaFuncAttributeMaxDynamicSharedMemorySize, SCORE_SMEM);

    k_prep<<<130, 256>>>(qe, kw, kb, b2, w1, b1, w2);
    k_bfrag<<<128, 256>>>();
    k_score_tc<<<256, 256, SCORE_SMEM>>>(tf, dens, w1, b1, w2);
    k_imp2<<<B * N / 256, 256>>>();
    k_rank<<<B * 16, 256>>>();
    k_compact<<<B, 1024>>>();
    k_gather<<<B * TOPK, 256>>>(tf, out);
}

// round 10
// speedup vs baseline: 1.6149x; 1.0390x over previous
#include <cuda_runtime.h>
#include <cuda_fp16.h>
#include <cstdint>

#define B 8
#define N 4096
#define D 1024
#define H 1024
#define NQ 64
#define H2 2048
#define TOPK 1024

// ---------------- scratch ----------------------------------------------------
__device__ __align__(16) float g_QWf[NQ * D];     // fp32 QW [q][d]
__device__ __align__(16) uint2 g_Bfrag[32768];    // fp16 fragment-ordered B
__device__ float g_qbi[NQ];                       // qb/32 + b2
__device__ __align__(16) float g_St[B * N * NQ];  // scores token-major
__device__ float g_pmax[B * 32 * NQ];
__device__ float g_psum[B * 32 * NQ];
__device__ float g_imp[B * N];
__device__ int   g_flag[B * N];
__device__ int   g_idx[B * TOPK];
__device__ float g_C1, g_C2;
__device__ int   g_bz;

// ---------------- helpers ----------------------------------------------------
__device__ __forceinline__ uint32_t pack_h2(float a, float b) {
    __half2 h = __floats2half2_rn(a, b);
    return *reinterpret_cast<uint32_t*>(&h);
}
__device__ __forceinline__ float2 unpack_h2(uint32_t u) {
    __half2 h = *reinterpret_cast<__half2*>(&u);
    return __half22float2(h);
}
__device__ __forceinline__ void mma_f16(float* d, const uint32_t* a, uint32_t b0, uint32_t b1) {
    asm volatile("mma.sync.aligned.m16n8k16.row.col.f32.f16.f16.f32 "
        "{%0,%1,%2,%3}, {%4,%5,%6,%7}, {%8,%9}, {%0,%1,%2,%3};"
        : "+f"(d[0]), "+f"(d[1]), "+f"(d[2]), "+f"(d[3])
        : "r"(a[0]), "r"(a[1]), "r"(a[2]), "r"(a[3]), "r"(b0), "r"(b1));
}
__device__ __forceinline__ void cp_async16(void* dst_smem, const void* src) {
    uint32_t d;
    asm("{ .reg .u64 t; cvta.to.shared.u64 t, %1; cvt.u32.u64 %0, t; }" : "=r"(d) : "l"(dst_smem));
    asm volatile("cp.async.cg.shared.global [%0], [%1], 16;" :: "r"(d), "l"(src) : "memory");
}
#define CP_COMMIT() asm volatile("cp.async.commit_group;" ::: "memory")
#define CP_WAIT(n)  asm volatile("cp.async.wait_group %0;" :: "n"(n) : "memory")

// ---------------- kernel 0: prep (QW GEMM + qbi + density consts) ------------
__global__ void __launch_bounds__(256) k_prep(const float* __restrict__ qe,
                                              const float* __restrict__ kw,
                                              const float* __restrict__ kb,
                                              const float* __restrict__ b2,
                                              const float* __restrict__ w1,
                                              const float* __restrict__ b1,
                                              const float* __restrict__ w2) {
    int tid = threadIdx.x;
    int bid = blockIdx.x;
    if (bid < 128) {
        __shared__ float skw[8][68];
        __shared__ float sqt[64][65];
        int d0 = bid * 8;
        int q = tid & 63, dp = tid >> 6;
        float acc0 = 0.f, acc1 = 0.f;
        for (int k0 = 0; k0 < H; k0 += 64) {
#pragma unroll
            for (int r = 0; r < 2; r++) {
                int idx = tid + 256 * r;
                skw[idx >> 6][idx & 63] = kw[(size_t)(d0 + (idx >> 6)) * H + k0 + (idx & 63)];
            }
#pragma unroll
            for (int r = 0; r < 4; r++) {
                int idx = tid + 256 * r;
                int row = idx >> 4, c4 = (idx & 15) * 4;
                float4 v = *(const float4*)(qe + (size_t)row * H + k0 + c4);
                sqt[c4 + 0][row] = v.x; sqt[c4 + 1][row] = v.y;
                sqt[c4 + 2][row] = v.z; sqt[c4 + 3][row] = v.w;
            }
            __syncthreads();
#pragma unroll 8
            for (int k = 0; k < 64; k++) {
                float qv = sqt[k][q];
                acc0 = fmaf(skw[dp][k], qv, acc0);
                acc1 = fmaf(skw[dp + 4][k], qv, acc1);
            }
            __syncthreads();
        }
        g_QWf[(size_t)q * D + d0 + dp] = acc0;
        g_QWf[(size_t)q * D + d0 + dp + 4] = acc1;
    } else if (bid == 128) {
        int w = tid >> 5, l = tid & 31;
        float b2v = b2[0];
#pragma unroll
        for (int qi = 0; qi < 8; qi++) {
            int q = w * 8 + qi;
            float acc = 0.f;
#pragma unroll
            for (int k = 0; k < 32; k++)
                acc = fmaf(qe[(size_t)q * H + k * 32 + l], kb[k * 32 + l], acc);
#pragma unroll
            for (int o = 16; o; o >>= 1) acc += __shfl_xor_sync(~0u, acc, o);
            if (l == 0) g_qbi[q] = acc * 0.03125f + b2v;
        }
    } else {
        __shared__ float r1[256], r2[256];
        __shared__ int rz[256];
        float c1 = 0.f, c2 = 0.f; int bz = 1;
        for (int j = tid; j < H2; j += 256) {
            float a = w1[j], c = w2[j];
            if (a > 0.f) c1 += a * c; else c2 += a * c;
            if (b1[j] != 0.f) bz = 0;
        }
        r1[tid] = c1; r2[tid] = c2; rz[tid] = bz;
        __syncthreads();
        for (int o = 128; o; o >>= 1) {
            if (tid < o) { r1[tid] += r1[tid + o]; r2[tid] += r2[tid + o]; rz[tid] &= rz[tid + o]; }
            __syncthreads();
        }
        if (tid == 0) { g_C1 = r1[0]; g_C2 = r2[0]; g_bz = rz[0]; }
    }
}

// ---------------- kernel 1: pack B into fp16 fragment order ------------------
__global__ void k_bfrag() {
    int t = blockIdx.x * 256 + threadIdx.x;   // < 32768
    int lane = t & 31, pl = (t >> 5) & 1, j = (t >> 6) & 7, s = (t >> 9) & 1, c = t >> 10;
    int q = j * 8 + (lane >> 2);
    int k0 = c * 32 + s * 16 + (lane & 3) * 2;
    const float* w = g_QWf + (size_t)q * D + k0;
    float f0 = w[0], f1 = w[1], f2 = w[8], f3 = w[9];
    uint32_t ha = pack_h2(f0, f1), hb = pack_h2(f2, f3);
    if (pl == 0) {
        g_Bfrag[t] = make_uint2(ha, hb);
    } else {
        float2 ca = unpack_h2(ha), cb = unpack_h2(hb);
        g_Bfrag[t] = make_uint2(pack_h2(f0 - ca.x, f1 - ca.y),
                                pack_h2(f2 - cb.x, f3 - cb.y));
    }
}

// ---------------- kernel 2: score GEMM (3-stage, frag-B, inline dbias) -------
// float offsets in dynamic smem
#define XB(s)  ((s) * 4096)            // 3 X buffers, 128 rows x 32 (swizzled)
#define PM_OFF 9216                    // inside XB region; free after mainloop
#define PZ_OFF 9472
#define BBF(s) (12288 + (s) * 2048)    // 3 B fragment buffers (1024 uint2)
#define SDB_OFF 18432
#define QBI_OFF 18560
#define SCORE_SMEM 74496               // 18624 floats

__global__ void __launch_bounds__(256, 2) k_score_tc(const float* __restrict__ x,
                                                     const float* __restrict__ dens,
                                                     const float* __restrict__ w1,
                                                     const float* __restrict__ b1,
                                                     const float* __restrict__ w2) {
    extern __shared__ float sm[];
    int tid = threadIdx.x, w = tid >> 5, l = tid & 31;
    int b = blockIdx.x >> 5, tile = blockIdx.x & 31;
    int n0 = tile << 7;
    int wm = w & 3, wn = w >> 2;
    const char* xg = (const char*)(x + ((size_t)(b * N + n0)) * D);
    const char* fg = (const char*)g_Bfrag;

    float acc[2][4][4] = {};

    int xrow = tid >> 1;                 // 0..127
    int xc0  = (tid & 1) * 4;            // chunk base 0 or 4

    auto issue = [&](int c) {
        int st = c % 3;
        float* xb = sm + XB(st);
        float* bb = sm + BBF(st);
#pragma unroll
        for (int i = 0; i < 4; i++) {
            int ch = xc0 + i;
            int chs = ch ^ ((xrow & 3) << 1);           // swizzled 16B chunk
            cp_async16(xb + xrow * 32 + chs * 4,
                       xg + (size_t)xrow * 4096 + (size_t)c * 128 + ch * 16);
        }
#pragma unroll
        for (int i = 0; i < 2; i++)
            cp_async16(bb + (tid + i * 256) * 4,
                       fg + (size_t)c * 8192 + (tid + i * 256) * 16);
        CP_COMMIT();
    };

    issue(0);
    issue(1);

    // ---- hoisted: density bias + qbi staging (overlaps with cp.async) ------
    if (tid < 128) {
        float d = dens[b * N + n0 + tid];
        float db;
        if (g_bz) {
            db = d * (d >= 0.f ? g_C1 : g_C2);
        } else {
            db = 0.f;
            for (int j = 0; j < H2; j++)
                db = fmaf(fmaxf(fmaf(d, w1[j], b1[j]), 0.f), w2[j], db);
        }
        sm[SDB_OFF + tid] = db;
    } else if (tid < 192) {
        sm[QBI_OFF + tid - 128] = g_qbi[tid - 128];
    }

#pragma unroll 3
    for (int c = 0; c < 32; c++) {
        CP_WAIT(1);
        __syncthreads();
        if (c + 2 < 32) issue(c + 2);
        int st = c % 3;
        const float* xb = sm + XB(st);
        const uint2* bb = (const uint2*)(sm + BBF(st));

#pragma unroll
        for (int s = 0; s < 2; s++) {
            // B fragments from smem (pre-split planes)
            uint2 b0f[4], b1f[4];
#pragma unroll
            for (int nt = 0; nt < 4; nt++) {
                int j = wn * 4 + nt;
                b0f[nt] = bb[((s * 8 + j) * 2 + 0) * 32 + l];
                b1f[nt] = bb[((s * 8 + j) * 2 + 1) * 32 + l];
            }
#pragma unroll
            for (int mt = 0; mt < 2; mt++) {
                int r  = wm * 32 + mt * 16 + (l >> 2);
                int p  = s * 8 + (l & 3);
                int sw0 = (p     ^ ((r & 3) << 2)) * 2;
                int sw2 = ((p+4) ^ ((r & 3) << 2)) * 2;
                int r8 = r + 8;
                int t0 = (p     ^ ((r8 & 3) << 2)) * 2;
                int t2 = ((p+4) ^ ((r8 & 3) << 2)) * 2;
                float2 A0 = *(const float2*)(xb + r  * 32 + sw0);
                float2 A1 = *(const float2*)(xb + r8 * 32 + t0);
                float2 A2 = *(const float2*)(xb + r  * 32 + sw2);
                float2 A3 = *(const float2*)(xb + r8 * 32 + t2);
                uint32_t a0[4], a1[4];
                a0[0] = pack_h2(A0.x, A0.y); a0[1] = pack_h2(A1.x, A1.y);
                a0[2] = pack_h2(A2.x, A2.y); a0[3] = pack_h2(A3.x, A3.y);
                float2 c0 = unpack_h2(a0[0]), c1 = unpack_h2(a0[1]);
                float2 c2 = unpack_h2(a0[2]), c3 = unpack_h2(a0[3]);
                a1[0] = pack_h2(A0.x - c0.x, A0.y - c0.y);
                a1[1] = pack_h2(A1.x - c1.x, A1.y - c1.y);
                a1[2] = pack_h2(A2.x - c2.x, A2.y - c2.y);
                a1[3] = pack_h2(A3.x - c3.x, A3.y - c3.y);
#pragma unroll
                for (int nt = 0; nt < 4; nt++) {
                    mma_f16(acc[mt][nt], a0, b0f[nt].x, b0f[nt].y);
                    mma_f16(acc[mt][nt], a0, b1f[nt].x, b1f[nt].y);
                    mma_f16(acc[mt][nt], a1, b0f[nt].x, b0f[nt].y);
                }
            }
        }
    }
    __syncthreads();

    // ---- epilogue: bias + stage token-major + store + softmax partials ------
    float* sS = sm;                         // [128 tok][68] = 8704 floats
#pragma unroll
    for (int mt = 0; mt < 2; mt++) {
        int r = wm * 32 + mt * 16 + (l >> 2);
        float d0 = sm[SDB_OFF + r], d1 = sm[SDB_OFF + r + 8];
#pragma unroll
        for (int nt = 0; nt < 4; nt++) {
            int q = wn * 32 + nt * 8 + (l & 3) * 2;
            float t0 = sm[QBI_OFF + q], t1 = sm[QBI_OFF + q + 1];
            sS[r * 68 + q]           = fmaf(acc[mt][nt][0], 0.03125f, t0 + d0);
            sS[r * 68 + q + 1]       = fmaf(acc[mt][nt][1], 0.03125f, t1 + d0);
            sS[(r + 8) * 68 + q]     = fmaf(acc[mt][nt][2], 0.03125f, t0 + d1);
            sS[(r + 8) * 68 + q + 1] = fmaf(acc[mt][nt][3], 0.03125f, t1 + d1);
        }
    }
    __syncthreads();

    {   // token-major coalesced store
        int tok = tid >> 1, h = tid & 1;
        float* dst = g_St + ((size_t)(b * N + n0 + tok)) * 64 + h * 32;
        const float* src = sS + tok * 68 + h * 32;
#pragma unroll
        for (int i = 0; i < 8; i++)
            *(float4*)(dst + i * 4) = *(const float4*)(src + i * 4);
    }

    {   // per-tile softmax partials (pm/pz live in the dead X-buffer region)
        int q = tid & 63, grp = tid >> 6;
        const float* col = sS + (grp * 32) * 68 + q;
        float m = -1e30f;
#pragma unroll
        for (int i = 0; i < 32; i++) m = fmaxf(m, col[i * 68]);
        float z = 0.f;
#pragma unroll
        for (int i = 0; i < 32; i++) z += expf(col[i * 68] - m);
        sm[PM_OFF + grp * 64 + q] = m;
        sm[PZ_OFF + grp * 64 + q] = z;
    }
    __syncthreads();
    if (tid < 64) {
        const float* pm = sm + PM_OFF;
        const float* pz = sm + PZ_OFF;
        float M = pm[tid];
        M = fmaxf(M, pm[64 + tid]);
        M = fmaxf(M, pm[128 + tid]);
        M = fmaxf(M, pm[192 + tid]);
        float Z = 0.f;
#pragma unroll
        for (int g = 0; g < 4; g++)
            Z += pz[g * 64 + tid] * expf(pm[g * 64 + tid] - M);
        g_pmax[(b * 32 + tile) * NQ + tid] = M;
        g_psum[(b * 32 + tile) * NQ + tid] = Z;
    }
}

// ---------------- kernel 3: importance (2 threads/token) ---------------------
__global__ void k_imp2() {
    __shared__ float sc[NQ];
    int blk = blockIdx.x, tid = threadIdx.x;
    int b = blk >> 5;                       // 32 blocks per batch
    if (tid < 64) {
        float M = -1e30f;
#pragma unroll 8
        for (int tl = 0; tl < 32; tl++)
            M = fmaxf(M, g_pmax[(b * 32 + tl) * NQ + tid]);
        float Z = 0.f;
#pragma unroll 8
        for (int tl = 0; tl < 32; tl++)
            Z += g_psum[(b * 32 + tl) * NQ + tid] * expf(g_pmax[(b * 32 + tl) * NQ + tid] - M);
        sc[tid] = M + logf(Z);
    }
    __syncthreads();
    int n = (blk & 31) * 128 + (tid >> 1);
    int half = tid & 1;
    const float4* row = (const float4*)(g_St + ((size_t)(b * N + n)) * 64 + half * 32);
    float best = -1e30f;
#pragma unroll
    for (int i = 0; i < 8; i++) {
        float4 v = row[i];
        int q = half * 32 + i * 4;
        best = fmaxf(best, fmaxf(fmaxf(v.x - sc[q], v.y - sc[q + 1]),
                                 fmaxf(v.z - sc[q + 2], v.w - sc[q + 3])));
    }
    best = fmaxf(best, __shfl_xor_sync(~0u, best, 1));
    if (half == 0) g_imp[b * N + n] = best;
}

// ---------------- kernel 4: exact rank (stable top-k) ------------------------
__global__ void __launch_bounds__(256) k_rank() {
    __shared__ unsigned long long key[N];
    int b   = blockIdx.x >> 4;
    int seg = blockIdx.x & 15;
    int tid = threadIdx.x;
    for (int i = tid; i < N; i += 256) {
        unsigned u = __float_as_uint(g_imp[b * N + i]);
        u ^= ((unsigned)(((int)u) >> 31)) | 0x80000000u;
        key[i] = ((unsigned long long)u << 12) | (unsigned)(N - 1 - i);
    }
    __syncthreads();
    int i = seg * 256 + tid;
    unsigned long long ki = key[i];
    int r = 0;
#pragma unroll 8
    for (int j = 0; j < N; j++) r += (key[j] > ki);
    g_flag[b * N + i] = (r < TOPK) ? 1 : 0;
}

// ---------------- kernel 5: compact selected indices -------------------------
__global__ void k_compact() {
    __shared__ unsigned words[N / 32];
    __shared__ int pre[N / 32];
    int b   = blockIdx.x;
    int tid = threadIdx.x;
#pragma unroll
    for (int cc = 0; cc < N / 1024; cc++) {
        int gi = cc * 1024 + tid;
        unsigned bal = __ballot_sync(~0u, g_flag[b * N + gi]);
        if ((tid & 31) == 0) words[gi >> 5] = bal;
    }
    __syncthreads();
    if (tid == 0) {
        int s = 0;
        for (int w = 0; w < N / 32; w++) { pre[w] = s; s += __popc(words[w]); }
    }
    __syncthreads();
#pragma unroll
    for (int cc = 0; cc < N / 1024; cc++) {
        int gi = cc * 1024 + tid;
        unsigned w = words[gi >> 5];
        if ((w >> (gi & 31)) & 1u) {
            int slot = pre[gi >> 5] + __popc(w & ((1u << (gi & 31)) - 1u));
            g_idx[b * TOPK + slot] = gi;
        }
    }
}

// ---------------- kernel 6: gather selected rows -----------------------------
__global__ void k_gather(const float* __restrict__ x, float* __restrict__ out) {
    int row = blockIdx.x;
    int b   = row >> 10;
    int i   = g_idx[row];
    const float4* src = (const float4*)(x + ((size_t)(b * N + i)) * D);
    float4* dst = (float4*)(out + (size_t)row * D);
    dst[threadIdx.x] = src[threadIdx.x];
}

// ---------------- launch -----------------------------------------------------
extern "C" void kernel_launch(void* const* d_in, const int* in_sizes, int n_in,
                              void* d_out, int out_size) {
    const float* tf   = (const float*)d_in[0];
    const float* dens = (const float*)d_in[1];
    const float* qe   = (const float*)d_in[2];
    const float* kw   = (const float*)d_in[3];
    const float* kb   = (const float*)d_in[4];
    const float* w1   = (const float*)d_in[5];
    const float* b1   = (const float*)d_in[6];
    const float* w2   = (const float*)d_in[7];
    const float* b2   = (const float*)d_in[8];
    float* out = (float*)d_out;

    cudaFuncSetAttribute(k_score_tc, cudaFuncAttributeMaxDynamicSharedMemorySize, SCORE_SMEM);

    k_prep<<<130, 256>>>(qe, kw, kb, b2, w1, b1, w2);
    k_bfrag<<<128, 256>>>();
    k_score_tc<<<256, 256, SCORE_SMEM>>>(tf, dens, w1, b1, w2);
    k_imp2<<<256, 256>>>();
    k_rank<<<B * 16, 256>>>();
    k_compact<<<B, 1024>>>();
    k_gather<<<B * TOPK, 256>>>(tf, out);
}